// round 14
// baseline (speedup 1.0000x reference)
#include <cuda_runtime.h>
#include <math_constants.h>

#define H_IMG 256
#define W_IMG 256
#define A_ANG 64
#define DC_DET 1024
#define NSAMP 512
#define FEAT 32
#define NPIX (H_IMG * W_IMG)
#define IMG4_W 257
#define NRAY (A_ANG * DC_DET)

#define PW 264
#define PH 258
#define PPLANE (PW * PH)

// ---------------- scratch (device globals: allocation-free) ----------------
__device__ float4 g_img4[IMG4_W * IMG4_W];
__device__ float4 g_rayA[NRAY];
__device__ float4 g_rayB[NRAY];
__device__ float g_hodd[1024];
__device__ float g_sino[NRAY];
__device__ float g_filt[NRAY];
__device__ float g_xinput[NPIX];
__device__ __align__(16) float g_feat1[FEAT * PPLANE];
__device__ __align__(16) float g_xforward[FEAT * PPLANE];
__device__ __align__(16) float g_hs[FEAT * PPLANE];
__device__ __align__(16) float g_t1[FEAT * PPLANE];
__device__ __align__(16) float g_t2[FEAT * PPLANE];

// ---------------- f32x2 packed-FMA helpers (Blackwell) ----------------
typedef unsigned long long u64t;
__device__ __forceinline__ u64t pk2(float x) {
    u64t r;
    asm("mov.b64 %0, {%1, %1};" : "=l"(r) : "f"(x));
    return r;
}
__device__ __forceinline__ void fma2(u64t& d, u64t a, u64t b) {
    asm("fma.rn.f32x2 %0, %1, %2, %0;" : "+l"(d) : "l"(a), "l"(b));
}
__device__ __forceinline__ void unpk2(float& lo, float& hi, u64t v) {
    asm("mov.b64 {%0, %1}, %2;" : "=f"(lo), "=f"(hi) : "l"(v));
}

// ---------------- merged prep (img4) + ramp IR + per-ray geometry -----------
__device__ __forceinline__ float img_tap(const float* __restrict__ img, int xi, int yi) {
    if ((unsigned)xi < (unsigned)W_IMG && (unsigned)yi < (unsigned)H_IMG)
        return __ldg(&img[yi * W_IMG + xi]);
    return 0.0f;
}

#define PREP_BLOCKS 259
#define RAMP_BLOCKS 4
#define GEOM_BLOCKS 256

__global__ void k_prepall(const float* __restrict__ img, const float* __restrict__ theta) {
    if (blockIdx.x < PREP_BLOCKS) {
        int i = blockIdx.x * 256 + threadIdx.x;
        if (i >= IMG4_W * IMG4_W) return;
        int yy = i / IMG4_W - 1;
        int xx = i - (yy + 1) * IMG4_W - 1;
        g_img4[i] = make_float4(img_tap(img, xx, yy), img_tap(img, xx + 1, yy),
                                img_tap(img, xx, yy + 1), img_tap(img, xx + 1, yy + 1));
        return;
    }
    if (blockIdx.x < PREP_BLOCKS + RAMP_BLOCKS) {
        int i = (blockIdx.x - PREP_BLOCKS) * 256 + threadIdx.x;
        float sh = sinf((float)(2 * i + 1) * 1.5339807878856412e-3f);  // pi/2048
        g_hodd[i] = -4.76837158203125e-7f / (sh * sh);                 // -1/2^21
        return;
    }
    int ray = (blockIdx.x - PREP_BLOCKS - RAMP_BLOCKS) * 256 + threadIdx.x;
    int a = ray >> 10;
    int dc = ray & 1023;
    float th = theta[a];
    float c = cosf(th), s = sinf(th);
    float srcx = 500.0f * c, srcy = 500.0f * s;
    float u = ((float)dc - 511.5f) * 2.0f;
    float dx = -1000.0f * c - u * s;
    float dy = -1000.0f * s + u * c;
    float L = sqrtf(dx * dx + dy * dy);

    const float lo = -128.51f, hi = 128.51f;
    float tlo = 0.0f, thi = 1.0f;
    if (fabsf(dx) > 1e-9f) {
        float ta = (lo - srcx) / dx, tb = (hi - srcx) / dx;
        tlo = fmaxf(tlo, fminf(ta, tb));
        thi = fminf(thi, fmaxf(ta, tb));
    } else if (srcx < lo || srcx > hi) { thi = -1.0f; }
    if (fabsf(dy) > 1e-9f) {
        float ta = (lo - srcy) / dy, tb = (hi - srcy) / dy;
        tlo = fmaxf(tlo, fminf(ta, tb));
        thi = fminf(thi, fmaxf(ta, tb));
    } else if (srcy < lo || srcy > hi) { thi = -1.0f; }

    int kmin = 1, kmax = 0;
    if (thi > tlo) {
        kmin = max((int)ceilf(tlo * (float)NSAMP - 0.5f) - 1, 0);
        kmax = min((int)floorf(thi * (float)NSAMP - 0.5f) + 1, NSAMP - 1);
    }
    g_rayA[ray] = make_float4(srcx, srcy, dx, dy);
    g_rayB[ray] = make_float4(__int_as_float(kmin), __int_as_float(kmax),
                              L * (1.0f / (float)NSAMP), 0.0f);
}

// ---------------- fan-beam forward projection (8 threads / ray, 4 chains) ---
__device__ __forceinline__ void ff_sample(int k, const float4& A, float& acc) {
    float t = ((float)k + 0.5f) * (1.0f / (float)NSAMP);
    float cx = fmaf(t, A.z, A.x) + 127.5f;
    float cy = fmaf(t, A.w, A.y) + 127.5f;
    float x0 = floorf(cx), y0 = floorf(cy);
    float fx = cx - x0, fy = cy - y0;
    int xi = (int)x0 + 1, yi = (int)y0 + 1;
    if ((unsigned)xi < (unsigned)IMG4_W && (unsigned)yi < (unsigned)IMG4_W) {
        float4 v = __ldg(&g_img4[yi * IMG4_W + xi]);
        float vx0 = fmaf(fx, v.y - v.x, v.x);
        float vx1 = fmaf(fx, v.w - v.z, v.z);
        acc += fmaf(fy, vx1 - vx0, vx0);
    }
}

__global__ void k_fanfwd() {
    int gid = blockIdx.x * blockDim.x + threadIdx.x;
    int ray = gid >> 3;
    int sub = gid & 7;
    float4 A = __ldg(&g_rayA[ray]);
    float4 B = __ldg(&g_rayB[ray]);
    int kmin = __float_as_int(B.x);
    int kmax = __float_as_int(B.y);
    float acc0 = 0.0f, acc1 = 0.0f, acc2 = 0.0f, acc3 = 0.0f;
    int k = kmin + sub;
    for (; k + 24 <= kmax; k += 32) {
        ff_sample(k, A, acc0);
        ff_sample(k + 8, A, acc1);
        ff_sample(k + 16, A, acc2);
        ff_sample(k + 24, A, acc3);
    }
    for (; k <= kmax; k += 8) ff_sample(k, A, acc0);
    float acc = (acc0 + acc2) + (acc1 + acc3);
    acc += __shfl_xor_sync(0xFFFFFFFFu, acc, 1);
    acc += __shfl_xor_sync(0xFFFFFFFFu, acc, 2);
    acc += __shfl_xor_sync(0xFFFFFFFFu, acc, 4);
    if (sub == 0) g_sino[ray] = acc * B.z;
}

// ---------------- ramp filter (closed-form IR from g_hodd) ----------------
__global__ void __launch_bounds__(256) k_filter(const float* __restrict__ obs) {
    __shared__ float xs[DC_DET];
    __shared__ float hodd[1024];
    int a = blockIdx.x;
    int tid = threadIdx.x;
    for (int i = tid; i < 1024; i += 256) hodd[i] = g_hodd[i];
    for (int i = tid; i < DC_DET; i += 256) xs[i] = g_sino[a * DC_DET + i];
    __syncthreads();

    int t = tid;
    int b2t = 2 * t;
    float a0 = 0.f, a1 = 0.f, a2 = 0.f, a3 = 0.f;
#pragma unroll 4
    for (int kb = 0; kb < 512; kb += 4) {
        float4 X0 = *(float4*)&xs[2 * kb];
        float4 X1 = *(float4*)&xs[2 * kb + 4];
        int e0 = (b2t - kb - 4) & 1023;
        float2 w01 = *(float2*)&hodd[e0];
        float2 w23 = *(float2*)&hodd[(e0 + 2) & 1023];
        float2 w45 = *(float2*)&hodd[(e0 + 4) & 1023];
        float H0 = w01.x, H1 = w01.y, H2 = w23.x, H3 = w23.y, H4 = w45.x, H5 = w45.y;
        a0 = fmaf(H3, X0.y, a0); a1 = fmaf(H4, X0.x, a1);
        a2 = fmaf(H4, X0.y, a2); a3 = fmaf(H5, X0.x, a3);
        a0 = fmaf(H2, X0.w, a0); a1 = fmaf(H3, X0.z, a1);
        a2 = fmaf(H3, X0.w, a2); a3 = fmaf(H4, X0.z, a3);
        a0 = fmaf(H1, X1.y, a0); a1 = fmaf(H2, X1.x, a1);
        a2 = fmaf(H2, X1.y, a2); a3 = fmaf(H3, X1.x, a3);
        a0 = fmaf(H0, X1.w, a0); a1 = fmaf(H1, X1.z, a1);
        a2 = fmaf(H1, X1.w, a2); a3 = fmaf(H2, X1.z, a3);
    }
    int n = 4 * t;
    float4 xc = *(float4*)&xs[n];
    float4 o4 = *(const float4*)&obs[a * DC_DET + n];
    float4 res;
    res.x = fmaf(0.5f, xc.x, a0) - o4.x;
    res.y = fmaf(0.5f, xc.y, a1) - o4.y;
    res.z = fmaf(0.5f, xc.z, a2) - o4.z;
    res.w = fmaf(0.5f, xc.w, a3) - o4.w;
    *(float4*)&g_filt[a * DC_DET + n] = res;
}

// ---------------- backprojection + x_input (4 independent chains) -----------
__global__ void __launch_bounds__(256) k_backproj(const float* __restrict__ theta,
                                                  const float* __restrict__ x_in,
                                                  const float* __restrict__ lam_p) {
    __shared__ float cs[A_ANG], ss[A_ANG];
    __shared__ float partial[8][33];
    int tid = threadIdx.x;
    if (tid < A_ANG) {
        float th = theta[tid];
        cs[tid] = cosf(th);
        ss[tid] = sinf(th);
    }
    __syncthreads();
    int lane = tid & 31;
    int wrp = tid >> 5;
    int pix = blockIdx.x * 32 + lane;
    int py = pix >> 8, px = pix & 255;
    float gx = (float)px - 127.5f;
    float gy = (float)py - 127.5f;
    float accq[4] = {0.0f, 0.0f, 0.0f, 0.0f};
    int a0 = wrp * 8;
#pragma unroll
    for (int j = 0; j < 8; ++j) {
        int a = a0 + j;
        float c = cs[a], s = ss[a];
        float xr = gx * c + gy * s;
        float yr = -gx * s + gy * c;
        float invd = __fdividef(1.0f, 500.0f - xr);
        float uu = yr * 1000.0f * invd;
        float wgt = 250000.0f * invd * invd;
        float iu = uu * 0.5f + 511.5f;
        float i0f = floorf(iu);
        float fr = iu - i0f;
        int i0 = (int)i0f;
        const float* row = g_filt + a * DC_DET;
        float v0 = __ldg(&row[i0]);
        float v1 = __ldg(&row[i0 + 1]);
        accq[j & 3] += wgt * fmaf(fr, v1 - v0, v0);
    }
    partial[wrp][lane] = (accq[0] + accq[2]) + (accq[1] + accq[3]);
    __syncthreads();
    if (wrp == 0) {
        float acc = partial[0][lane] + partial[1][lane] + partial[2][lane] + partial[3][lane] +
                    partial[4][lane] + partial[5][lane] + partial[6][lane] + partial[7][lane];
        float lam = __ldg(lam_p);
        g_xinput[pix] = x_in[pix] - lam * acc * (float)(CUDART_PI / 64.0);
    }
}

// ---------------- conv 1->32 + relu : g_xinput -> g_feat1 (padded) ----------
__global__ void k_conv1f(const float* __restrict__ w) {
    __shared__ float ws[9][32];
    int tid = threadIdx.x;
    for (int i = tid; i < 288; i += 256) {
        int k = i >> 5, oc = i & 31;
        ws[k][oc] = w[oc * 9 + k];
    }
    __syncthreads();
    int pix = blockIdx.x * 128 + (tid >> 1);
    int half = tid & 1;
    int py = pix >> 8, px = pix & 255;
    float pv[9];
#pragma unroll
    for (int dy = 0; dy < 3; ++dy)
#pragma unroll
        for (int dxk = 0; dxk < 3; ++dxk) {
            int yy = py - 1 + dy, xx = px - 1 + dxk;
            pv[dy * 3 + dxk] = ((unsigned)yy < (unsigned)H_IMG && (unsigned)xx < (unsigned)W_IMG)
                                   ? __ldg(&g_xinput[yy * W_IMG + xx]) : 0.0f;
        }
    float acc[16];
#pragma unroll
    for (int o = 0; o < 16; ++o) acc[o] = 0.0f;
    int ob = half * 16;
#pragma unroll
    for (int k = 0; k < 9; ++k) {
#pragma unroll
        for (int o4 = 0; o4 < 4; ++o4) {
            float4 wv = *(const float4*)&ws[k][ob + o4 * 4];
            acc[o4 * 4 + 0] = fmaf(pv[k], wv.x, acc[o4 * 4 + 0]);
            acc[o4 * 4 + 1] = fmaf(pv[k], wv.y, acc[o4 * 4 + 1]);
            acc[o4 * 4 + 2] = fmaf(pv[k], wv.z, acc[o4 * 4 + 2]);
            acc[o4 * 4 + 3] = fmaf(pv[k], wv.w, acc[o4 * 4 + 3]);
        }
    }
    int base = (py + 1) * PW + px + 5;
#pragma unroll
    for (int o = 0; o < 16; ++o)
        g_feat1[(ob + o) * PPLANE + base] = fmaxf(acc[o], 0.0f);
}

// ---------------- conv 32->32 core: padded in/out, 4 px/thread, 16 oc -------
// NOTE: this tile4 formulation is empirically ~3x faster than the 2px/thread
// variants tried in R11/R12 — do not restructure without SASS evidence.
template <bool SOFT>
__device__ __forceinline__ void conv32_tile4(const float* __restrict__ in,
                                             float* __restrict__ out,
                                             float* __restrict__ out2,
                                             const float* __restrict__ thr_p,
                                             const float* __restrict__ w,
                                             int tile, int half, int tid) {
    __shared__ __align__(16) float ws[32][9][16];
    __shared__ __align__(16) float ins[8][18][40];
    int ocbase = half * 16;
    for (int i = tid; i < 32 * 9 * 16; i += 128) {
        int ocl = i / 288;
        int r = i - ocl * 288;
        int ic = r / 9;
        int k = r - ic * 9;
        ws[ic][k][ocl] = w[(ocbase + ocl) * 288 + r];
    }
    int bx = tile & 7, by = tile >> 3;
    int x0 = bx * 32, y0 = by * 16;
    int lx = tid & 15, ly = tid >> 4;

    u64t acc[4][8];
#pragma unroll
    for (int p = 0; p < 4; ++p)
#pragma unroll
        for (int o = 0; o < 8; ++o) acc[p][o] = 0ull;

    for (int cc = 0; cc < 4; ++cc) {
        __syncthreads();
        for (int i = tid; i < 8 * 18 * 9; i += 128) {
            int icc = i / 162;
            int rem = i - icc * 162;
            int rr = rem / 9;
            int c4 = rem - rr * 9;
            const float4* src = (const float4*)(in + (cc * 8 + icc) * PPLANE +
                                                (y0 + rr) * PW + x0 + 4);
            *(float4*)&ins[icc][rr][c4 * 4] = src[c4];
        }
        __syncthreads();
#pragma unroll
        for (int icc = 0; icc < 8; ++icc) {
            int ic = cc * 8 + icc;
#pragma unroll
            for (int dy = 0; dy < 3; ++dy)
#pragma unroll
                for (int dxk = 0; dxk < 3; ++dxk) {
                    int k = dy * 3 + dxk;
                    u64t p0 = pk2(ins[icc][ly + dy][lx + dxk]);
                    u64t p1 = pk2(ins[icc][ly + dy][lx + 16 + dxk]);
                    u64t p2 = pk2(ins[icc][ly + 8 + dy][lx + dxk]);
                    u64t p3 = pk2(ins[icc][ly + 8 + dy][lx + 16 + dxk]);
#pragma unroll
                    for (int o4 = 0; o4 < 4; ++o4) {
                        ulonglong2 wq = *(const ulonglong2*)&ws[ic][k][o4 * 4];
                        fma2(acc[0][o4 * 2 + 0], p0, wq.x);
                        fma2(acc[0][o4 * 2 + 1], p0, wq.y);
                        fma2(acc[1][o4 * 2 + 0], p1, wq.x);
                        fma2(acc[1][o4 * 2 + 1], p1, wq.y);
                        fma2(acc[2][o4 * 2 + 0], p2, wq.x);
                        fma2(acc[2][o4 * 2 + 1], p2, wq.y);
                        fma2(acc[3][o4 * 2 + 0], p3, wq.x);
                        fma2(acc[3][o4 * 2 + 1], p3, wq.y);
                    }
                }
        }
    }
    float thr = SOFT ? __ldg(thr_p) : 0.0f;
    int xs4[4], ys4[4];
    xs4[0] = x0 + lx;      ys4[0] = y0 + ly;
    xs4[1] = x0 + lx + 16; ys4[1] = y0 + ly;
    xs4[2] = x0 + lx;      ys4[2] = y0 + ly + 8;
    xs4[3] = x0 + lx + 16; ys4[3] = y0 + ly + 8;
#pragma unroll
    for (int p = 0; p < 4; ++p) {
        int base = (ys4[p] + 1) * PW + xs4[p] + 5;
#pragma unroll
        for (int j = 0; j < 8; ++j) {
            float va, vb;
            unpk2(va, vb, acc[p][j]);
            int oA = ocbase + 2 * j, oB = oA + 1;
            if (!SOFT) { va = fmaxf(va, 0.0f); vb = fmaxf(vb, 0.0f); }
            out[oA * PPLANE + base] = va;
            out[oB * PPLANE + base] = vb;
            if (SOFT) {
                float ma = fmaxf(fabsf(va) - thr, 0.0f);
                float mb = fmaxf(fabsf(vb) - thr, 0.0f);
                out2[oA * PPLANE + base] = (va > 0.0f) ? ma : ((va < 0.0f) ? -ma : 0.0f);
                out2[oB * PPLANE + base] = (vb > 0.0f) ? mb : ((vb < 0.0f) ? -mb : 0.0f);
            }
        }
    }
}

__global__ void __launch_bounds__(128) k_conv32a(const float* __restrict__ w,
                                                 const float* __restrict__ thr_p) {
    conv32_tile4<true>(g_feat1, g_xforward, g_hs, thr_p, w,
                       blockIdx.x & 127, blockIdx.x >> 7, threadIdx.x);
}

__global__ void __launch_bounds__(128) k_conv32b(const float* __restrict__ w) {
    int which = blockIdx.x >> 8;
    const float* in = which ? g_xforward : g_hs;
    float* out = which ? g_t2 : g_t1;
    conv32_tile4<false>(in, out, nullptr, nullptr, w,
                        blockIdx.x & 127, (blockIdx.x >> 7) & 1, threadIdx.x);
}

// ---------------- conv 32->1 (padded input), merged pair --------------------
__global__ void k_conv32to1(const float* __restrict__ w, float* __restrict__ outbase) {
    int sub = blockIdx.x >> 8;
    int tile = blockIdx.x & 255;
    const float* __restrict__ in = sub ? g_t2 : g_t1;
    float* __restrict__ out = outbase + sub * NPIX;
    __shared__ float ws[288];
    __shared__ __align__(16) float ins[8][18][20];
    int tid = threadIdx.x;
    for (int i = tid; i < 288; i += 256) ws[i] = w[i];
    int bx = tile & 15, by = tile >> 4;
    int tx0 = bx * 16, ty0 = by * 16;
    int lx = tid & 15, ly = tid >> 4;
    float acc = 0.0f;
    for (int cc = 0; cc < 4; ++cc) {
        __syncthreads();
        for (int i = tid; i < 8 * 18 * 5; i += 256) {
            int icc = i / 90;
            int rem = i - icc * 90;
            int rr = rem / 5;
            int c4 = rem - rr * 5;
            const float4* src = (const float4*)(in + (cc * 8 + icc) * PPLANE +
                                                (ty0 + rr) * PW + tx0 + 4);
            *(float4*)&ins[icc][rr][c4 * 4] = src[c4];
        }
        __syncthreads();
#pragma unroll
        for (int icc = 0; icc < 8; ++icc) {
            int ic = cc * 8 + icc;
#pragma unroll
            for (int dy = 0; dy < 3; ++dy)
#pragma unroll
                for (int dxk = 0; dxk < 3; ++dxk)
                    acc = fmaf(ins[icc][ly + dy][lx + dxk], ws[ic * 9 + dy * 3 + dxk], acc);
        }
    }
    int pix = (ty0 + ly) * W_IMG + tx0 + lx;
    out[pix] = sub ? (acc - g_xinput[pix]) : acc;
}

// ---------------- launch ----------------
extern "C" void kernel_launch(void* const* d_in, const int* in_sizes, int n_in,
                              void* d_out, int out_size) {
    const float* x        = (const float*)d_in[0];
    const float* theta    = (const float*)d_in[1];
    const float* sinogram = (const float*)d_in[2];
    const float* lam      = (const float*)d_in[3];
    const float* thr      = (const float*)d_in[4];
    const float* w1f      = (const float*)d_in[5];
    const float* w2f      = (const float*)d_in[6];
    const float* w1b      = (const float*)d_in[7];
    const float* w2b      = (const float*)d_in[8];
    float* out = (float*)d_out;

    k_prepall<<<PREP_BLOCKS + RAMP_BLOCKS + GEOM_BLOCKS, 256>>>(x, theta);  // #1
    k_fanfwd<<<2048, 256>>>();                                              // #2 4 chains
    k_filter<<<A_ANG, 256>>>(sinogram);                                     // #3
    k_backproj<<<2048, 256>>>(theta, x, lam);                               // #4 4 chains (capture)
    k_conv1f<<<512, 256>>>(w1f);                                            // #5
    k_conv32a<<<256, 128>>>(w2f, thr);                                      // #6 tile4 (frozen)
    k_conv32b<<<512, 128>>>(w1b);                                           // #7 tile4 (frozen)
    k_conv32to1<<<512, 256>>>(w2b, out);                                    // #8
}

// round 15
// speedup vs baseline: 1.0340x; 1.0340x over previous
#include <cuda_runtime.h>
#include <math_constants.h>

#define H_IMG 256
#define W_IMG 256
#define A_ANG 64
#define DC_DET 1024
#define NSAMP 512
#define FEAT 32
#define NPIX (H_IMG * W_IMG)
#define IMG4_W 257
#define NRAY (A_ANG * DC_DET)

#define PW 264
#define PH 258
#define PPLANE (PW * PH)

// ---------------- scratch (device globals: allocation-free) ----------------
__device__ float4 g_img4[IMG4_W * IMG4_W];
__device__ float4 g_rayA[NRAY];
__device__ float4 g_rayB[NRAY];
__device__ float g_hodd[1024];
__device__ float g_sino[NRAY];
__device__ float g_filt[NRAY];
__device__ float g_xinput[NPIX];
__device__ __align__(16) float g_feat1[FEAT * PPLANE];
__device__ __align__(16) float g_xforward[FEAT * PPLANE];
__device__ __align__(16) float g_hs[FEAT * PPLANE];
__device__ __align__(16) float g_t1[FEAT * PPLANE];
__device__ __align__(16) float g_t2[FEAT * PPLANE];

// ---------------- f32x2 packed-FMA helpers (Blackwell) ----------------
typedef unsigned long long u64t;
__device__ __forceinline__ u64t pk2(float x) {
    u64t r;
    asm("mov.b64 %0, {%1, %1};" : "=l"(r) : "f"(x));
    return r;
}
__device__ __forceinline__ void fma2(u64t& d, u64t a, u64t b) {
    asm("fma.rn.f32x2 %0, %1, %2, %0;" : "+l"(d) : "l"(a), "l"(b));
}
__device__ __forceinline__ void unpk2(float& lo, float& hi, u64t v) {
    asm("mov.b64 {%0, %1}, %2;" : "=f"(lo), "=f"(hi) : "l"(v));
}

// ---------------- merged prep (img4) + ramp IR + per-ray geometry -----------
__device__ __forceinline__ float img_tap(const float* __restrict__ img, int xi, int yi) {
    if ((unsigned)xi < (unsigned)W_IMG && (unsigned)yi < (unsigned)H_IMG)
        return __ldg(&img[yi * W_IMG + xi]);
    return 0.0f;
}

#define PREP_BLOCKS 259
#define RAMP_BLOCKS 4
#define GEOM_BLOCKS 256

__global__ void k_prepall(const float* __restrict__ img, const float* __restrict__ theta) {
    if (blockIdx.x < PREP_BLOCKS) {
        int i = blockIdx.x * 256 + threadIdx.x;
        if (i >= IMG4_W * IMG4_W) return;
        int yy = i / IMG4_W - 1;
        int xx = i - (yy + 1) * IMG4_W - 1;
        g_img4[i] = make_float4(img_tap(img, xx, yy), img_tap(img, xx + 1, yy),
                                img_tap(img, xx, yy + 1), img_tap(img, xx + 1, yy + 1));
        return;
    }
    if (blockIdx.x < PREP_BLOCKS + RAMP_BLOCKS) {
        int i = (blockIdx.x - PREP_BLOCKS) * 256 + threadIdx.x;
        float sh = sinf((float)(2 * i + 1) * 1.5339807878856412e-3f);  // pi/2048
        g_hodd[i] = -4.76837158203125e-7f / (sh * sh);                 // -1/2^21
        return;
    }
    int ray = (blockIdx.x - PREP_BLOCKS - RAMP_BLOCKS) * 256 + threadIdx.x;
    int a = ray >> 10;
    int dc = ray & 1023;
    float th = theta[a];
    float c = cosf(th), s = sinf(th);
    float srcx = 500.0f * c, srcy = 500.0f * s;
    float u = ((float)dc - 511.5f) * 2.0f;
    float dx = -1000.0f * c - u * s;
    float dy = -1000.0f * s + u * c;
    float L = sqrtf(dx * dx + dy * dy);

    const float lo = -128.51f, hi = 128.51f;
    float tlo = 0.0f, thi = 1.0f;
    if (fabsf(dx) > 1e-9f) {
        float ta = (lo - srcx) / dx, tb = (hi - srcx) / dx;
        tlo = fmaxf(tlo, fminf(ta, tb));
        thi = fminf(thi, fmaxf(ta, tb));
    } else if (srcx < lo || srcx > hi) { thi = -1.0f; }
    if (fabsf(dy) > 1e-9f) {
        float ta = (lo - srcy) / dy, tb = (hi - srcy) / dy;
        tlo = fmaxf(tlo, fminf(ta, tb));
        thi = fminf(thi, fmaxf(ta, tb));
    } else if (srcy < lo || srcy > hi) { thi = -1.0f; }

    int kmin = 1, kmax = 0;
    if (thi > tlo) {
        kmin = max((int)ceilf(tlo * (float)NSAMP - 0.5f) - 1, 0);
        kmax = min((int)floorf(thi * (float)NSAMP - 0.5f) + 1, NSAMP - 1);
    }
    g_rayA[ray] = make_float4(srcx, srcy, dx, dy);
    g_rayB[ray] = make_float4(__int_as_float(kmin), __int_as_float(kmax),
                              L * (1.0f / (float)NSAMP), 0.0f);
}

// ---------------- fan-beam forward projection (8 threads / ray) -------------
__device__ __forceinline__ void ff_sample(int k, const float4& A, float& acc) {
    float t = ((float)k + 0.5f) * (1.0f / (float)NSAMP);
    float cx = fmaf(t, A.z, A.x) + 127.5f;
    float cy = fmaf(t, A.w, A.y) + 127.5f;
    float x0 = floorf(cx), y0 = floorf(cy);
    float fx = cx - x0, fy = cy - y0;
    int xi = (int)x0 + 1, yi = (int)y0 + 1;
    if ((unsigned)xi < (unsigned)IMG4_W && (unsigned)yi < (unsigned)IMG4_W) {
        float4 v = __ldg(&g_img4[yi * IMG4_W + xi]);
        float vx0 = fmaf(fx, v.y - v.x, v.x);
        float vx1 = fmaf(fx, v.w - v.z, v.z);
        acc += fmaf(fy, vx1 - vx0, vx0);
    }
}

__global__ void k_fanfwd() {
    int gid = blockIdx.x * blockDim.x + threadIdx.x;
    int ray = gid >> 3;
    int sub = gid & 7;
    float4 A = __ldg(&g_rayA[ray]);
    float4 B = __ldg(&g_rayB[ray]);
    int kmin = __float_as_int(B.x);
    int kmax = __float_as_int(B.y);
    float acc0 = 0.0f, acc1 = 0.0f;
    int k = kmin + sub;
    for (; k + 8 <= kmax; k += 16) {
        ff_sample(k, A, acc0);
        ff_sample(k + 8, A, acc1);
    }
    if (k <= kmax) ff_sample(k, A, acc0);
    float acc = acc0 + acc1;
    acc += __shfl_xor_sync(0xFFFFFFFFu, acc, 1);
    acc += __shfl_xor_sync(0xFFFFFFFFu, acc, 2);
    acc += __shfl_xor_sync(0xFFFFFFFFu, acc, 4);
    if (sub == 0) g_sino[ray] = acc * B.z;
}

// ---------------- ramp filter (closed-form IR from g_hodd) ----------------
__global__ void __launch_bounds__(256) k_filter(const float* __restrict__ obs) {
    __shared__ float xs[DC_DET];
    __shared__ float hodd[1024];
    int a = blockIdx.x;
    int tid = threadIdx.x;
    for (int i = tid; i < 1024; i += 256) hodd[i] = g_hodd[i];
    for (int i = tid; i < DC_DET; i += 256) xs[i] = g_sino[a * DC_DET + i];
    __syncthreads();

    int t = tid;
    int b2t = 2 * t;
    float a0 = 0.f, a1 = 0.f, a2 = 0.f, a3 = 0.f;
#pragma unroll 4
    for (int kb = 0; kb < 512; kb += 4) {
        float4 X0 = *(float4*)&xs[2 * kb];
        float4 X1 = *(float4*)&xs[2 * kb + 4];
        int e0 = (b2t - kb - 4) & 1023;
        float2 w01 = *(float2*)&hodd[e0];
        float2 w23 = *(float2*)&hodd[(e0 + 2) & 1023];
        float2 w45 = *(float2*)&hodd[(e0 + 4) & 1023];
        float H0 = w01.x, H1 = w01.y, H2 = w23.x, H3 = w23.y, H4 = w45.x, H5 = w45.y;
        a0 = fmaf(H3, X0.y, a0); a1 = fmaf(H4, X0.x, a1);
        a2 = fmaf(H4, X0.y, a2); a3 = fmaf(H5, X0.x, a3);
        a0 = fmaf(H2, X0.w, a0); a1 = fmaf(H3, X0.z, a1);
        a2 = fmaf(H3, X0.w, a2); a3 = fmaf(H4, X0.z, a3);
        a0 = fmaf(H1, X1.y, a0); a1 = fmaf(H2, X1.x, a1);
        a2 = fmaf(H2, X1.y, a2); a3 = fmaf(H3, X1.x, a3);
        a0 = fmaf(H0, X1.w, a0); a1 = fmaf(H1, X1.z, a1);
        a2 = fmaf(H1, X1.w, a2); a3 = fmaf(H2, X1.z, a3);
    }
    int n = 4 * t;
    float4 xc = *(float4*)&xs[n];
    float4 o4 = *(const float4*)&obs[a * DC_DET + n];
    float4 res;
    res.x = fmaf(0.5f, xc.x, a0) - o4.x;
    res.y = fmaf(0.5f, xc.y, a1) - o4.y;
    res.z = fmaf(0.5f, xc.z, a2) - o4.z;
    res.w = fmaf(0.5f, xc.w, a3) - o4.w;
    *(float4*)&g_filt[a * DC_DET + n] = res;
}

// ---------------- backprojection + x_input (R13 form) -----------------------
__global__ void __launch_bounds__(256) k_backproj(const float* __restrict__ theta,
                                                  const float* __restrict__ x_in,
                                                  const float* __restrict__ lam_p) {
    __shared__ float cs[A_ANG], ss[A_ANG];
    __shared__ float partial[8][33];
    int tid = threadIdx.x;
    if (tid < A_ANG) {
        float th = theta[tid];
        cs[tid] = cosf(th);
        ss[tid] = sinf(th);
    }
    __syncthreads();
    int lane = tid & 31;
    int wrp = tid >> 5;
    int pix = blockIdx.x * 32 + lane;
    int py = pix >> 8, px = pix & 255;
    float gx = (float)px - 127.5f;
    float gy = (float)py - 127.5f;
    float accA = 0.0f, accB = 0.0f;
    int a0 = wrp * 8;
#pragma unroll
    for (int j = 0; j < 8; j += 2) {
#pragma unroll
        for (int half = 0; half < 2; ++half) {
            int a = a0 + j + half;
            float c = cs[a], s = ss[a];
            float xr = gx * c + gy * s;
            float yr = -gx * s + gy * c;
            float invd = __fdividef(1.0f, 500.0f - xr);
            float uu = yr * 1000.0f * invd;
            float wgt = 250000.0f * invd * invd;
            float iu = uu * 0.5f + 511.5f;
            float i0f = floorf(iu);
            float fr = iu - i0f;
            int i0 = (int)i0f;
            const float* row = g_filt + a * DC_DET;
            float v0 = __ldg(&row[i0]);
            float v1 = __ldg(&row[i0 + 1]);
            float term = wgt * fmaf(fr, v1 - v0, v0);
            if (half == 0) accA += term; else accB += term;
        }
    }
    partial[wrp][lane] = accA + accB;
    __syncthreads();
    if (wrp == 0) {
        float acc = partial[0][lane] + partial[1][lane] + partial[2][lane] + partial[3][lane] +
                    partial[4][lane] + partial[5][lane] + partial[6][lane] + partial[7][lane];
        float lam = __ldg(lam_p);
        g_xinput[pix] = x_in[pix] - lam * acc * (float)(CUDART_PI / 64.0);
    }
}

// ---------------- conv 1->32 + relu : g_xinput -> g_feat1 (padded) ----------
__global__ void k_conv1f(const float* __restrict__ w) {
    __shared__ float ws[9][32];
    int tid = threadIdx.x;
    for (int i = tid; i < 288; i += 256) {
        int k = i >> 5, oc = i & 31;
        ws[k][oc] = w[oc * 9 + k];
    }
    __syncthreads();
    int pix = blockIdx.x * 128 + (tid >> 1);
    int half = tid & 1;
    int py = pix >> 8, px = pix & 255;
    float pv[9];
#pragma unroll
    for (int dy = 0; dy < 3; ++dy)
#pragma unroll
        for (int dxk = 0; dxk < 3; ++dxk) {
            int yy = py - 1 + dy, xx = px - 1 + dxk;
            pv[dy * 3 + dxk] = ((unsigned)yy < (unsigned)H_IMG && (unsigned)xx < (unsigned)W_IMG)
                                   ? __ldg(&g_xinput[yy * W_IMG + xx]) : 0.0f;
        }
    float acc[16];
#pragma unroll
    for (int o = 0; o < 16; ++o) acc[o] = 0.0f;
    int ob = half * 16;
#pragma unroll
    for (int k = 0; k < 9; ++k) {
#pragma unroll
        for (int o4 = 0; o4 < 4; ++o4) {
            float4 wv = *(const float4*)&ws[k][ob + o4 * 4];
            acc[o4 * 4 + 0] = fmaf(pv[k], wv.x, acc[o4 * 4 + 0]);
            acc[o4 * 4 + 1] = fmaf(pv[k], wv.y, acc[o4 * 4 + 1]);
            acc[o4 * 4 + 2] = fmaf(pv[k], wv.z, acc[o4 * 4 + 2]);
            acc[o4 * 4 + 3] = fmaf(pv[k], wv.w, acc[o4 * 4 + 3]);
        }
    }
    int base = (py + 1) * PW + px + 5;
#pragma unroll
    for (int o = 0; o < 16; ++o)
        g_feat1[(ob + o) * PPLANE + base] = fmaxf(acc[o], 0.0f);
}

// ---------------- conv 32->32 core: padded in/out, 4 px/thread, 16 oc -------
// FROZEN: empirically ~3x faster than 2px/thread variants (R11/R12 evidence).
template <bool SOFT>
__device__ __forceinline__ void conv32_tile4(const float* __restrict__ in,
                                             float* __restrict__ out,
                                             float* __restrict__ out2,
                                             const float* __restrict__ thr_p,
                                             const float* __restrict__ w,
                                             int tile, int half, int tid) {
    __shared__ __align__(16) float ws[32][9][16];
    __shared__ __align__(16) float ins[8][18][40];
    int ocbase = half * 16;
    for (int i = tid; i < 32 * 9 * 16; i += 128) {
        int ocl = i / 288;
        int r = i - ocl * 288;
        int ic = r / 9;
        int k = r - ic * 9;
        ws[ic][k][ocl] = w[(ocbase + ocl) * 288 + r];
    }
    int bx = tile & 7, by = tile >> 3;
    int x0 = bx * 32, y0 = by * 16;
    int lx = tid & 15, ly = tid >> 4;

    u64t acc[4][8];
#pragma unroll
    for (int p = 0; p < 4; ++p)
#pragma unroll
        for (int o = 0; o < 8; ++o) acc[p][o] = 0ull;

    for (int cc = 0; cc < 4; ++cc) {
        __syncthreads();
        for (int i = tid; i < 8 * 18 * 9; i += 128) {
            int icc = i / 162;
            int rem = i - icc * 162;
            int rr = rem / 9;
            int c4 = rem - rr * 9;
            const float4* src = (const float4*)(in + (cc * 8 + icc) * PPLANE +
                                                (y0 + rr) * PW + x0 + 4);
            *(float4*)&ins[icc][rr][c4 * 4] = src[c4];
        }
        __syncthreads();
#pragma unroll
        for (int icc = 0; icc < 8; ++icc) {
            int ic = cc * 8 + icc;
#pragma unroll
            for (int dy = 0; dy < 3; ++dy)
#pragma unroll
                for (int dxk = 0; dxk < 3; ++dxk) {
                    int k = dy * 3 + dxk;
                    u64t p0 = pk2(ins[icc][ly + dy][lx + dxk]);
                    u64t p1 = pk2(ins[icc][ly + dy][lx + 16 + dxk]);
                    u64t p2 = pk2(ins[icc][ly + 8 + dy][lx + dxk]);
                    u64t p3 = pk2(ins[icc][ly + 8 + dy][lx + 16 + dxk]);
#pragma unroll
                    for (int o4 = 0; o4 < 4; ++o4) {
                        ulonglong2 wq = *(const ulonglong2*)&ws[ic][k][o4 * 4];
                        fma2(acc[0][o4 * 2 + 0], p0, wq.x);
                        fma2(acc[0][o4 * 2 + 1], p0, wq.y);
                        fma2(acc[1][o4 * 2 + 0], p1, wq.x);
                        fma2(acc[1][o4 * 2 + 1], p1, wq.y);
                        fma2(acc[2][o4 * 2 + 0], p2, wq.x);
                        fma2(acc[2][o4 * 2 + 1], p2, wq.y);
                        fma2(acc[3][o4 * 2 + 0], p3, wq.x);
                        fma2(acc[3][o4 * 2 + 1], p3, wq.y);
                    }
                }
        }
    }
    float thr = SOFT ? __ldg(thr_p) : 0.0f;
    int xs4[4], ys4[4];
    xs4[0] = x0 + lx;      ys4[0] = y0 + ly;
    xs4[1] = x0 + lx + 16; ys4[1] = y0 + ly;
    xs4[2] = x0 + lx;      ys4[2] = y0 + ly + 8;
    xs4[3] = x0 + lx + 16; ys4[3] = y0 + ly + 8;
#pragma unroll
    for (int p = 0; p < 4; ++p) {
        int base = (ys4[p] + 1) * PW + xs4[p] + 5;
#pragma unroll
        for (int j = 0; j < 8; ++j) {
            float va, vb;
            unpk2(va, vb, acc[p][j]);
            int oA = ocbase + 2 * j, oB = oA + 1;
            if (!SOFT) { va = fmaxf(va, 0.0f); vb = fmaxf(vb, 0.0f); }
            out[oA * PPLANE + base] = va;
            out[oB * PPLANE + base] = vb;
            if (SOFT) {
                float ma = fmaxf(fabsf(va) - thr, 0.0f);
                float mb = fmaxf(fabsf(vb) - thr, 0.0f);
                out2[oA * PPLANE + base] = (va > 0.0f) ? ma : ((va < 0.0f) ? -ma : 0.0f);
                out2[oB * PPLANE + base] = (vb > 0.0f) ? mb : ((vb < 0.0f) ? -mb : 0.0f);
            }
        }
    }
}

__global__ void __launch_bounds__(128) k_conv32a(const float* __restrict__ w,
                                                 const float* __restrict__ thr_p) {
    conv32_tile4<true>(g_feat1, g_xforward, g_hs, thr_p, w,
                       blockIdx.x & 127, blockIdx.x >> 7, threadIdx.x);
}

__global__ void __launch_bounds__(128) k_conv32b(const float* __restrict__ w) {
    int which = blockIdx.x >> 8;
    const float* in = which ? g_xforward : g_hs;
    float* out = which ? g_t2 : g_t1;
    conv32_tile4<false>(in, out, nullptr, nullptr, w,
                        blockIdx.x & 127, (blockIdx.x >> 7) & 1, threadIdx.x);
}

// ---------------- conv 32->1 merged pair via f32x2 ---------------------------
// Both branches (g_t1 -> x_pred, g_t2 -> x_est) share weights. Pack inputs as
// interleaved (t1,t2) float2 in smem and weights as duplicated (w,w) pairs:
// inner loop = LDS.64 + LDS.64 + FMA2 (3 slots/tap vs 6 across two old blocks).
__global__ void __launch_bounds__(256) k_conv32to1(const float* __restrict__ w,
                                                   float* __restrict__ outbase) {
    __shared__ __align__(8) float ws2[288 * 2];      // (w,w) pairs, 2.3 KB
    __shared__ __align__(16) float ins[8][18][40];   // (t1,t2) interleaved, 23 KB
    int tid = threadIdx.x;
    int tile = blockIdx.x;
    for (int i = tid; i < 288; i += 256) {
        float wv = w[i];
        ws2[2 * i] = wv;
        ws2[2 * i + 1] = wv;
    }
    int bx = tile & 15, by = tile >> 4;
    int tx0 = bx * 16, ty0 = by * 16;
    int lx = tid & 15, ly = tid >> 4;
    u64t acc = 0ull;
    for (int cc = 0; cc < 4; ++cc) {
        __syncthreads();
        // fill: 8 ic x 18 rows x 5 float4-locs; interleave t1/t2 per element
        for (int i = tid; i < 8 * 18 * 5; i += 256) {
            int icc = i / 90;
            int rem = i - icc * 90;
            int rr = rem / 5;
            int c4 = rem - rr * 5;
            int off = (cc * 8 + icc) * PPLANE + (ty0 + rr) * PW + tx0 + 4 + c4 * 4;
            float4 a4 = *(const float4*)(g_t1 + off);
            float4 b4 = *(const float4*)(g_t2 + off);
            float* dst = &ins[icc][rr][c4 * 8];
            *(float4*)dst = make_float4(a4.x, b4.x, a4.y, b4.y);
            *(float4*)(dst + 4) = make_float4(a4.z, b4.z, a4.w, b4.w);
        }
        __syncthreads();
#pragma unroll
        for (int icc = 0; icc < 8; ++icc) {
            int ic = cc * 8 + icc;
#pragma unroll
            for (int dy = 0; dy < 3; ++dy)
#pragma unroll
                for (int dxk = 0; dxk < 3; ++dxk) {
                    u64t p = *(const u64t*)&ins[icc][ly + dy][2 * (lx + dxk)];
                    u64t wv = *(const u64t*)&ws2[2 * (ic * 9 + dy * 3 + dxk)];
                    fma2(acc, p, wv);
                }
        }
    }
    float v1, v2;
    unpk2(v1, v2, acc);
    int pix = (ty0 + ly) * W_IMG + tx0 + lx;
    outbase[pix] = v1;                          // x_pred
    outbase[NPIX + pix] = v2 - g_xinput[pix];   // symloss
}

// ---------------- launch ----------------
extern "C" void kernel_launch(void* const* d_in, const int* in_sizes, int n_in,
                              void* d_out, int out_size) {
    const float* x        = (const float*)d_in[0];
    const float* theta    = (const float*)d_in[1];
    const float* sinogram = (const float*)d_in[2];
    const float* lam      = (const float*)d_in[3];
    const float* thr      = (const float*)d_in[4];
    const float* w1f      = (const float*)d_in[5];
    const float* w2f      = (const float*)d_in[6];
    const float* w1b      = (const float*)d_in[7];
    const float* w2b      = (const float*)d_in[8];
    float* out = (float*)d_out;

    k_prepall<<<PREP_BLOCKS + RAMP_BLOCKS + GEOM_BLOCKS, 256>>>(x, theta);  // #1
    k_fanfwd<<<2048, 256>>>();                                              // #2 (R13)
    k_filter<<<A_ANG, 256>>>(sinogram);                                     // #3
    k_backproj<<<2048, 256>>>(theta, x, lam);                               // #4 (R13, capture)
    k_conv1f<<<512, 256>>>(w1f);                                            // #5
    k_conv32a<<<256, 128>>>(w2f, thr);                                      // #6 frozen
    k_conv32b<<<512, 128>>>(w1b);                                           // #7 frozen
    k_conv32to1<<<256, 256>>>(w2b, out);                                    // #8 f32x2 merged
}